// round 15
// baseline (speedup 1.0000x reference)
#include <cuda_runtime.h>
#include <cuda_fp16.h>
#include <math.h>
#include <stdint.h>

constexpr int MT = 32768;
constexpr int D  = 256;

// ---------------- smem: 3-stage ring ----------------
// A planes: 128 rows x 64B ; B plane: 64 rows x 64B
constexpr int A_PLANE   = 128 * 64;            // 8192
constexpr int B_PLANE   = 64 * 64;             // 4096
constexpr int T_AHI = 0, T_ALO = A_PLANE, T_B = 2 * A_PLANE;
constexpr int STG_BYTES = 2 * A_PLANE + B_PLANE;   // 20480
constexpr int NSTAGE    = 3;
constexpr int SMEM_TOTAL = NSTAGE * STG_BYTES;     // 61440

// ---------------- device scratch ----------------
__device__ __half g_actHi[2][(size_t)MT * D];
__device__ __half g_actLo[2][(size_t)MT * D];
__device__ __half g_W[4][D * D];     // [n][k] folded fp16 weights
__device__ float g_bias[4][D];
__device__ float g_sum[3 * D];
__device__ float g_sq[3 * D];

// ---------------- helpers ----------------
__device__ __forceinline__ uint32_t smem_u32(const void* p) {
    return (uint32_t)__cvta_generic_to_shared(p);
}
__device__ __forceinline__ void cp16(uint32_t sdst, const void* gsrc) {
    asm volatile("cp.async.cg.shared.global [%0], [%1], 16;\n" :: "r"(sdst), "l"(gsrc));
}
#define CP_COMMIT asm volatile("cp.async.commit_group;\n" ::: "memory")

__device__ __forceinline__ float gelu_exact(float x) {
    return 0.5f * x * (1.0f + erff(x * 0.70710678118654752f));
}
__device__ __forceinline__ void split_f16(float x, __half& hi, __half& lo) {
    hi = __float2half(x);
    lo = __float2half(x - __half2float(hi));
}

#define LDSM4(r, addr) \
    asm volatile("ldmatrix.sync.aligned.m8n8.x4.shared.b16 {%0,%1,%2,%3}, [%4];" \
                 : "=r"((r)[0]), "=r"((r)[1]), "=r"((r)[2]), "=r"((r)[3]) : "r"(addr))
#define MMA(acc, a, b0_, b1_) \
    asm volatile("mma.sync.aligned.m16n8k16.row.col.f32.f16.f16.f32 " \
                 "{%0,%1,%2,%3}, {%4,%5,%6,%7}, {%8,%9}, {%0,%1,%2,%3};" \
                 : "+f"((acc)[0]), "+f"((acc)[1]), "+f"((acc)[2]), "+f"((acc)[3]) \
                 : "r"((a)[0]), "r"((a)[1]), "r"((a)[2]), "r"((a)[3]), \
                   "r"(b0_), "r"(b1_))

// ================= prep0: zero stats + gather/split + W1 fold =================
__global__ __launch_bounds__(256)
void prep0_kernel(const int* __restrict__ ids, const float* __restrict__ table,
                  const float* __restrict__ W1, const float* __restrict__ b1) {
    const int tid = threadIdx.x, blk = blockIdx.x;
    if (blk < 256) {
        const int col2 = (tid & 127) * 2;
        const int rsub = tid >> 7;
        uint32_t* dstH = (uint32_t*)g_actHi[0];
        uint32_t* dstL = (uint32_t*)g_actLo[0];
#pragma unroll 4
        for (int i = 0; i < 64; i++) {
            int row = blk * 128 + rsub + i * 2;
            int id  = __ldg(ids + row);
            float2 x = *(const float2*)(table + (size_t)id * D + col2);
            union { __half h[2]; uint32_t u; } ph, pl;
            split_f16(x.x, ph.h[0], pl.h[0]);
            split_f16(x.y, ph.h[1], pl.h[1]);
            size_t o = ((size_t)row * D + col2) >> 1;
            dstH[o] = ph.u; dstL[o] = pl.u;
        }
    } else {
        const int n = blk - 256;
        if (blk == 256) {
            for (int i = tid; i < 3 * D; i += 256) { g_sum[i] = 0.f; g_sq[i] = 0.f; }
        }
        g_W[0][n * D + tid] = __float2half(W1[(size_t)tid * D + n]);
        if (tid == 0) g_bias[0][n] = b1[n];
    }
}

// ================= per-layer fold =================
__global__ __launch_bounds__(256)
void fold_kernel(const float* __restrict__ W, const float* __restrict__ b,
                 const float* __restrict__ gamma, const float* __restrict__ beta,
                 int L, int sl) {
    __shared__ float red[256];
    const int n = blockIdx.x, k = threadIdx.x;
    const float inv_m = 1.0f / (float)MT;
    float mu  = g_sum[sl * D + k] * inv_m;
    float var = g_sq[sl * D + k] * inv_m - mu * mu;
    float a = rsqrtf(var + 1e-5f) * gamma[k];
    float c = beta[k] - mu * a;
    float w = W[(size_t)k * D + n];
    g_W[L][n * D + k] = __float2half(a * w);
    red[k] = c * w;
    __syncthreads();
#pragma unroll
    for (int s = 128; s > 0; s >>= 1) {
        if (k < s) red[k] += red[k + s];
        __syncthreads();
    }
    if (k == 0) g_bias[L][n] = b[n] + red[0];
}

// ================= layer kernel: 128x64 tile, 3 CTAs/SM, 3-stage k32 ring =================
template <bool FINAL>
__global__ __launch_bounds__(256, 3)
void layer_kernel(const __half* __restrict__ Ahi,
                  const __half* __restrict__ Alo,
                  int wl, int so,
                  __half* __restrict__ Ohi,
                  __half* __restrict__ Olo,
                  float* __restrict__ Ofp)
{
    extern __shared__ char smem[];
    const uint32_t sb = smem_u32(smem);
    const int tid  = threadIdx.x;
    const int lane = tid & 31;
    const int wid  = tid >> 5;
    const int wm   = wid >> 1;        // 0..3  (32-row slab)
    const int wn   = wid & 1;         // 0..1  (32-col half)
    const int n0   = blockIdx.x * 64;
    const int m0   = blockIdx.y * 128;

    const __half* __restrict__ W = g_W[wl];

    // cp.async mapping: A planes: row=tid>>1, segs {2(tid&1), +1}; B: row=tid>>2, seg=tid&3
    const int lrow = tid >> 1;
    const int lsp  = (tid & 1) * 2;
    const uint32_t lkey = (uint32_t)((lrow >> 1) & 3);
    const int brow_l = tid >> 2;
    const uint32_t bsegx = (uint32_t)((tid & 3) ^ ((brow_l >> 1) & 3));

    auto load_stage = [&](int ch) {
        const uint32_t st = sb + (ch % NSTAGE) * STG_BYTES;
        const int kof = ch * 32;
        const size_t ga = (size_t)(m0 + lrow) * D + kof;
        const uint32_t rbase = st + lrow * 64;
#pragma unroll
        for (int i = 0; i < 2; i++) {
            const uint32_t seg = lsp + i;
            const uint32_t d = rbase + ((seg ^ lkey) << 4);
            cp16(d + T_AHI, Ahi + ga + seg * 8);
            cp16(d + T_ALO, Alo + ga + seg * 8);
        }
        cp16(st + T_B + brow_l * 64 + (bsegx << 4),
             W + (size_t)(n0 + brow_l) * D + kof + (tid & 3) * 8);
    };

    load_stage(0); CP_COMMIT;
    load_stage(1); CP_COMMIT;

    float acc[2][4][4];
#pragma unroll
    for (int mt = 0; mt < 2; mt++)
#pragma unroll
        for (int n8 = 0; n8 < 4; n8++)
#pragma unroll
            for (int q = 0; q < 4; q++) acc[mt][n8][q] = 0.f;

    // ldmatrix offsets (XOR-swizzled, k16 toggles bit5)
    const int arow = wm * 32 + (lane & 15);
    const uint32_t aOff = (uint32_t)arow * 64
        + ((((uint32_t)(lane >> 4)) ^ (uint32_t)((arow >> 1) & 3)) << 4);
    const int brow = wn * 32 + (lane & 7) + ((lane >> 4) << 3);
    const uint32_t bOff = (uint32_t)brow * 64
        + ((((uint32_t)((lane >> 3) & 1)) ^ (uint32_t)((brow >> 1) & 3)) << 4);

#pragma unroll 1
    for (int ch = 0; ch < 8; ch++) {
        asm volatile("cp.async.wait_group 1;" ::: "memory");
        __syncthreads();
        if (ch + 2 < 8) load_stage(ch + 2);
        CP_COMMIT;   // always commit (uniform wait arithmetic)

        const uint32_t st = sb + (ch % NSTAGE) * STG_BYTES;
#pragma unroll
        for (int k16 = 0; k16 < 2; k16++) {
            uint32_t bf[2][4];
            uint32_t af[2][4];
#pragma unroll
            for (int nt = 0; nt < 2; nt++)
                LDSM4(bf[nt], (st + T_B + bOff + nt * 1024) ^ (k16 << 5));
#pragma unroll
            for (int mt = 0; mt < 2; mt++)
                LDSM4(af[mt], (st + T_AHI + aOff + mt * 1024) ^ (k16 << 5));
#pragma unroll
            for (int nt = 0; nt < 2; nt++)
#pragma unroll
                for (int j = 0; j < 2; j++)
#pragma unroll
                    for (int mt = 0; mt < 2; mt++)
                        MMA(acc[mt][nt * 2 + j], af[mt], bf[nt][j * 2], bf[nt][j * 2 + 1]);
#pragma unroll
            for (int mt = 0; mt < 2; mt++)
                LDSM4(af[mt], (st + T_ALO + aOff + mt * 1024) ^ (k16 << 5));
#pragma unroll
            for (int nt = 0; nt < 2; nt++)
#pragma unroll
                for (int j = 0; j < 2; j++)
#pragma unroll
                    for (int mt = 0; mt < 2; mt++)
                        MMA(acc[mt][nt * 2 + j], af[mt], bf[nt][j * 2], bf[nt][j * 2 + 1]);
        }
    }

    // ---------------- epilogue ----------------
    const int r0base = m0 + wm * 32 + (lane >> 2);
    const float2* bp = (const float2*)(g_bias[wl] + n0);
#pragma unroll
    for (int n8 = 0; n8 < 4; n8++) {
        const int colL = wn * 32 + n8 * 8 + (lane & 3) * 2;
        const float2 bb = __ldg(bp + (colL >> 1));
        const float b0 = bb.x, b1 = bb.y;
        float s0 = 0.f, s1 = 0.f, q0 = 0.f, q1 = 0.f;
#pragma unroll
        for (int mt = 0; mt < 2; mt++) {
#pragma unroll
            for (int h = 0; h < 2; h++) {
                float v0 = gelu_exact(acc[mt][n8][h * 2 + 0] + b0);
                float v1 = gelu_exact(acc[mt][n8][h * 2 + 1] + b1);
                int row = r0base + mt * 16 + h * 8;
                if (FINAL) {
                    *(float2*)(Ofp + (size_t)row * D + n0 + colL) = make_float2(v0, v1);
                } else {
                    s0 += v0; s1 += v1; q0 += v0 * v0; q1 += v1 * v1;
                    union { __half hh[2]; uint32_t u; } ph, pl;
                    split_f16(v0, ph.hh[0], pl.hh[0]);
                    split_f16(v1, ph.hh[1], pl.hh[1]);
                    size_t o = ((size_t)row * D + n0 + colL) >> 1;
                    ((uint32_t*)Ohi)[o] = ph.u;
                    ((uint32_t*)Olo)[o] = pl.u;
                }
            }
        }
        if (!FINAL) {
#pragma unroll
            for (int off = 4; off < 32; off <<= 1) {
                s0 += __shfl_xor_sync(0xFFFFFFFFu, s0, off);
                s1 += __shfl_xor_sync(0xFFFFFFFFu, s1, off);
                q0 += __shfl_xor_sync(0xFFFFFFFFu, q0, off);
                q1 += __shfl_xor_sync(0xFFFFFFFFu, q1, off);
            }
            if (lane < 4) {
                int c = so * D + n0 + wn * 32 + n8 * 8 + lane * 2;
                atomicAdd(&g_sum[c],     s0);
                atomicAdd(&g_sum[c + 1], s1);
                atomicAdd(&g_sq[c],      q0);
                atomicAdd(&g_sq[c + 1],  q1);
            }
        }
    }
}

// ================= launch =================
extern "C" void kernel_launch(void* const* d_in, const int* in_sizes, int n_in,
                              void* d_out, int out_size) {
    const int*   ids   = (const int*)d_in[0];
    const float* table = (const float*)d_in[1];
    const float* W1 = (const float*)d_in[2];
    const float* b1 = (const float*)d_in[3];
    const float* W2 = (const float*)d_in[4];
    const float* b2 = (const float*)d_in[5];
    const float* W3 = (const float*)d_in[6];
    const float* b3 = (const float*)d_in[7];
    const float* W4 = (const float*)d_in[8];
    const float* b4 = (const float*)d_in[9];
    const float* g1  = (const float*)d_in[10];
    const float* be1 = (const float*)d_in[11];
    const float* g2  = (const float*)d_in[12];
    const float* be2 = (const float*)d_in[13];
    const float* g3  = (const float*)d_in[14];
    const float* be3 = (const float*)d_in[15];
    float* out = (float*)d_out;

    __half *h0, *l0;
    cudaGetSymbolAddress((void**)&h0, g_actHi);
    cudaGetSymbolAddress((void**)&l0, g_actLo);
    __half* h1 = h0 + (size_t)MT * D;
    __half* l1 = l0 + (size_t)MT * D;

    static bool attr_set = false;
    if (!attr_set) {
        cudaFuncSetAttribute(layer_kernel<false>,
                             cudaFuncAttributeMaxDynamicSharedMemorySize, SMEM_TOTAL);
        cudaFuncSetAttribute(layer_kernel<true>,
                             cudaFuncAttributeMaxDynamicSharedMemorySize, SMEM_TOTAL);
        attr_set = true;
    }

    dim3 grid(4, 256);   // (n/64, m/128)

    prep0_kernel<<<512, 256>>>(ids, table, W1, b1);

    layer_kernel<false><<<grid, 256, SMEM_TOTAL>>>(h0, l0, 0, 0, h1, l1, nullptr);
    fold_kernel<<<256, 256>>>(W2, b2, g1, be1, 1, 0);
    layer_kernel<false><<<grid, 256, SMEM_TOTAL>>>(h1, l1, 1, 1, h0, l0, nullptr);
    fold_kernel<<<256, 256>>>(W3, b3, g2, be2, 2, 1);
    layer_kernel<false><<<grid, 256, SMEM_TOTAL>>>(h0, l0, 2, 2, h1, l1, nullptr);
    fold_kernel<<<256, 256>>>(W4, b4, g3, be3, 3, 2);
    layer_kernel<true><<<grid, 256, SMEM_TOTAL>>>(h1, l1, 3, -1, nullptr, nullptr, out);
}